// round 5
// baseline (speedup 1.0000x reference)
#include <cuda_runtime.h>

#define N_NODES 100000
#define N_EDGES 600000
#define E_TOT   700000      // edges + self loops
#define D       128
#define SCAN_B  1024
#define NB      ((N_NODES + SCAN_B - 1) / SCAN_B)   // 98
#define MEAN_B  256

typedef unsigned long long u64;

// ---------------- scratch: __device__ globals only (no allocations) ----------------
__device__ __align__(16) float g_h[(size_t)N_NODES * D];   // post-GEMM features
__device__ __align__(16) float g_o[(size_t)N_NODES * D];   // layer output
__device__ __align__(16) float2 g_wp[(D / 2) * D];         // k-pair-packed weights
__device__ float g_as[N_NODES];
__device__ float g_ad[N_NODES];
__device__ int   g_deg[N_NODES];
__device__ int   g_incl[N_NODES];
__device__ int   g_bsum[NB];
__device__ int   g_bpre[NB];
__device__ int   g_rp[N_NODES + 1];   // CSR row_ptr (by dst)
__device__ int   g_cur[N_NODES];      // scatter cursor
__device__ int   g_col[E_TOT];        // src node per incoming edge
__device__ float g_part[MEAN_B * D];

// ---------------- f32x2 helpers ----------------
__device__ __forceinline__ u64 ffma2(u64 a, u64 b, u64 c) {
    u64 d;
    asm("fma.rn.f32x2 %0, %1, %2, %3;" : "=l"(d) : "l"(a), "l"(b), "l"(c));
    return d;
}
__device__ __forceinline__ float f2sum(u64 v) {
    float lo = __uint_as_float((unsigned)(v & 0xffffffffu));
    float hi = __uint_as_float((unsigned)(v >> 32));
    return lo + hi;
}

// ---------------- CSR build (edge_index is int32: [src x E | dst x E]) ------------
__global__ void k_deg_init() {
    int i = blockIdx.x * blockDim.x + threadIdx.x;
    if (i < N_NODES) g_deg[i] = 1;   // self loop
}

__global__ void k_deg_count(const int* __restrict__ ei) {
    int e = blockIdx.x * blockDim.x + threadIdx.x;
    if (e < N_EDGES) {
        int d = ei[N_EDGES + e];
        if ((unsigned)d < N_NODES) atomicAdd(&g_deg[d], 1);
    }
}

__global__ void __launch_bounds__(SCAN_B) k_scan1() {
    __shared__ int s[SCAN_B];
    int tl = threadIdx.x;
    int t  = blockIdx.x * SCAN_B + tl;
    int v  = (t < N_NODES) ? g_deg[t] : 0;
    s[tl] = v;
    __syncthreads();
    #pragma unroll
    for (int off = 1; off < SCAN_B; off <<= 1) {
        int add = (tl >= off) ? s[tl - off] : 0;
        __syncthreads();
        s[tl] += add;
        __syncthreads();
    }
    if (t < N_NODES) g_incl[t] = s[tl];
    if (tl == SCAN_B - 1) g_bsum[blockIdx.x] = s[tl];
}

__global__ void k_scan2() {
    __shared__ int s[128];
    int t = threadIdx.x;
    int v = (t < NB) ? g_bsum[t] : 0;
    s[t] = v;
    __syncthreads();
    #pragma unroll
    for (int off = 1; off < 128; off <<= 1) {
        int add = (t >= off) ? s[t - off] : 0;
        __syncthreads();
        s[t] += add;
        __syncthreads();
    }
    if (t < NB) g_bpre[t] = s[t] - v;   // exclusive prefix of block sums
}

__global__ void k_scan3() {
    int t = blockIdx.x * blockDim.x + threadIdx.x;
    if (t < N_NODES) {
        int S = g_incl[t] + g_bpre[t / SCAN_B];   // inclusive prefix
        g_rp[t + 1] = S;
        g_cur[t]    = S - g_deg[t];
        if (t == 0) g_rp[0] = 0;
    }
}

__global__ void k_scatter(const int* __restrict__ ei) {
    int e = blockIdx.x * blockDim.x + threadIdx.x;
    if (e >= E_TOT) return;
    int s, d;
    if (e < N_EDGES) { s = ei[e]; d = ei[N_EDGES + e]; }
    else             { s = e - N_EDGES; d = s; }
    if ((unsigned)s >= N_NODES || (unsigned)d >= N_NODES) return;
    int pos = atomicAdd(&g_cur[d], 1);
    g_col[pos] = s;
}

// ---------------- pack W into k-pair-interleaved layout ----------------
// g_wp[kp*D + c] = { W[2kp][c], W[2kp+1][c] }
__global__ void k_wpack(const float* __restrict__ W) {
    int t = blockIdx.x * blockDim.x + threadIdx.x;   // 8192
    if (t < (D / 2) * D) {
        int kp = t / D, c = t % D;
        g_wp[t] = make_float2(W[(2 * kp) * D + c], W[(2 * kp + 1) * D + c]);
    }
}

// ---------------- GEMM via FFMA2: g_h = X*W, g_as = h.a_src, g_ad = h.a_dst -------
// 256 thr, 64 rows x 128 cols; lane owns cols {lane, lane+32, lane+64, lane+96}
__global__ void __launch_bounds__(256, 2) k_gemm(
    const float* __restrict__ Xext, int use_ext,
    const float* __restrict__ avs, const float* __restrict__ avd)
{
    __shared__ float  Xs[64 * D];        // 32 KB
    __shared__ float2 Wp_s[8 * D];       // 8 KB (one k-chunk of 16 = 8 k-pairs)

    const float* X = use_ext ? Xext : g_o;
    const int tid  = threadIdx.x;
    const int row0 = blockIdx.x * 64;

    // stage X tile
    {
        float4* Xs4 = (float4*)Xs;
        const float4* X4 = (const float4*)X;
        #pragma unroll
        for (int i = tid; i < 64 * D / 4; i += 256) {
            int r  = i / (D / 4);
            int gr = row0 + r;
            Xs4[i] = (gr < N_NODES) ? X4[(size_t)gr * (D / 4) + (i % (D / 4))]
                                    : make_float4(0.f, 0.f, 0.f, 0.f);
        }
    }

    const int warp  = tid >> 5;
    const int lane  = tid & 31;
    const int rbase = warp * 8;

    u64 acc[8][4];
    #pragma unroll
    for (int i = 0; i < 8; i++)
        #pragma unroll
        for (int j = 0; j < 4; j++) acc[i][j] = 0ull;

    for (int kc = 0; kc < 8; kc++) {       // 8 chunks of 16 k (8 k-pairs)
        __syncthreads();
        #pragma unroll
        for (int i = tid; i < 8 * D; i += 256) Wp_s[i] = g_wp[kc * (8 * D) + i];
        __syncthreads();

        #pragma unroll
        for (int kp = 0; kp < 8; kp++) {
            int kg = kc * 16 + kp * 2;
            u64 x2[8];
            #pragma unroll
            for (int i = 0; i < 8; i++)
                x2[i] = *(const u64*)&Xs[(rbase + i) * D + kg];   // broadcast LDS.64
            u64 w2[4];
            #pragma unroll
            for (int j = 0; j < 4; j++)
                w2[j] = *(const u64*)&Wp_s[kp * D + lane + 32 * j]; // conflict-free
            #pragma unroll
            for (int i = 0; i < 8; i++)
                #pragma unroll
                for (int j = 0; j < 4; j++)
                    acc[i][j] = ffma2(x2[i], w2[j], acc[i][j]);
        }
    }

    float a_s[4], a_d[4];
    #pragma unroll
    for (int j = 0; j < 4; j++) { a_s[j] = avs[lane + 32 * j]; a_d[j] = avd[lane + 32 * j]; }

    #pragma unroll
    for (int i = 0; i < 8; i++) {
        int gr = row0 + rbase + i;
        float r[4];
        #pragma unroll
        for (int j = 0; j < 4; j++) r[j] = f2sum(acc[i][j]);
        if (gr < N_NODES) {
            #pragma unroll
            for (int j = 0; j < 4; j++)
                g_h[(size_t)gr * D + lane + 32 * j] = r[j];   // 4 coalesced STG.32
        }
        float ps = r[0]*a_s[0] + r[1]*a_s[1] + r[2]*a_s[2] + r[3]*a_s[3];
        float pd = r[0]*a_d[0] + r[1]*a_d[1] + r[2]*a_d[2] + r[3]*a_d[3];
        #pragma unroll
        for (int off = 16; off; off >>= 1) {
            ps += __shfl_xor_sync(0xffffffffu, ps, off);
            pd += __shfl_xor_sync(0xffffffffu, pd, off);
        }
        if (lane == 0 && gr < N_NODES) { g_as[gr] = ps; g_ad[gr] = pd; }
    }
}

// ---------------- warp-per-node softmax + aggregation (no atomics) ----------------
__device__ __forceinline__ float leaky02(float e) {
    return fmaxf(e, 0.f) + 0.2f * fminf(e, 0.f);
}

__global__ void __launch_bounds__(256) k_node_agg(int do_relu, const float* __restrict__ b)
{
    int node = (blockIdx.x * blockDim.x + threadIdx.x) >> 5;
    int lane = threadIdx.x & 31;
    if (node >= N_NODES) return;

    int beg = g_rp[node];
    int end = g_rp[node + 1];
    float ad = g_ad[node];

    // pass 1: max
    float mx = -3.4e38f;
    for (int j = beg + lane; j < end; j += 32)
        mx = fmaxf(mx, leaky02(g_as[g_col[j]] + ad));
    #pragma unroll
    for (int off = 16; off; off >>= 1)
        mx = fmaxf(mx, __shfl_xor_sync(0xffffffffu, mx, off));

    // pass 2: denom
    float den = 0.f;
    for (int j = beg + lane; j < end; j += 32)
        den += __expf(leaky02(g_as[g_col[j]] + ad) - mx);
    #pragma unroll
    for (int off = 16; off; off >>= 1)
        den += __shfl_xor_sync(0xffffffffu, den, off);
    float inv = 1.f / den;

    // pass 3: feature accumulate (lane owns 4 columns)
    float4 acc = make_float4(0.f, 0.f, 0.f, 0.f);
    for (int j = beg; j < end; j++) {
        int s = g_col[j];                          // warp-uniform broadcast
        float w = __expf(leaky02(g_as[s] + ad) - mx) * inv;
        float4 hv = *(const float4*)&g_h[(size_t)s * D + lane * 4];
        acc.x = fmaf(w, hv.x, acc.x);
        acc.y = fmaf(w, hv.y, acc.y);
        acc.z = fmaf(w, hv.z, acc.z);
        acc.w = fmaf(w, hv.w, acc.w);
    }

    const float4 b4 = *(const float4*)&b[lane * 4];
    acc.x += b4.x; acc.y += b4.y; acc.z += b4.z; acc.w += b4.w;
    if (do_relu) {
        acc.x = fmaxf(acc.x, 0.f); acc.y = fmaxf(acc.y, 0.f);
        acc.z = fmaxf(acc.z, 0.f); acc.w = fmaxf(acc.w, 0.f);
    }
    *(float4*)&g_o[(size_t)node * D + lane * 4] = acc;
}

// ---------------- mean over nodes ----------------
__global__ void k_mean1() {
    int c = threadIdx.x;   // 128 threads = 128 cols
    float acc = 0.f;
    for (int r = blockIdx.x; r < N_NODES; r += MEAN_B)
        acc += g_o[(size_t)r * D + c];
    g_part[blockIdx.x * D + c] = acc;
}

__global__ void k_mean2(float* __restrict__ out) {
    int c = threadIdx.x;
    float s = 0.f;
    for (int i = 0; i < MEAN_B; i++) s += g_part[i * D + c];
    out[c] = s * (1.0f / N_NODES);
}

// ---------------- driver: kernel launches ONLY ----------------
extern "C" void kernel_launch(void* const* d_in, const int* in_sizes, int n_in,
                              void* d_out, int out_size)
{
    const float* x   = (const float*)d_in[0];
    const int*   ei  = (const int*)d_in[1];      // int32: [src x E | dst x E]
    const float* W1  = (const float*)d_in[2];
    const float* as1 = (const float*)d_in[3];
    const float* ad1 = (const float*)d_in[4];
    const float* b1  = (const float*)d_in[5];
    const float* W2  = (const float*)d_in[6];
    const float* as2 = (const float*)d_in[7];
    const float* ad2 = (const float*)d_in[8];
    const float* b2  = (const float*)d_in[9];
    float* out = (float*)d_out;

    // CSR build (identical for both layers)
    k_deg_init <<<(N_NODES + 255) / 256, 256>>>();
    k_deg_count<<<(N_EDGES + 255) / 256, 256>>>(ei);
    k_scan1    <<<NB, SCAN_B>>>();
    k_scan2    <<<1, 128>>>();
    k_scan3    <<<(N_NODES + 255) / 256, 256>>>();
    k_scatter  <<<(E_TOT + 255) / 256, 256>>>(ei);

    // layer 1: x -> g_h -> g_o (relu)
    k_wpack   <<<(D * D / 2 + 255) / 256, 256>>>(W1);
    k_gemm    <<<(N_NODES + 63) / 64, 256>>>(x, 1, as1, ad1);
    k_node_agg<<<(N_NODES * 32 + 255) / 256, 256>>>(1, b1);

    // layer 2: g_o -> g_h -> g_o
    k_wpack   <<<(D * D / 2 + 255) / 256, 256>>>(W2);
    k_gemm    <<<(N_NODES + 63) / 64, 256>>>(nullptr, 0, as2, ad2);
    k_node_agg<<<(N_NODES * 32 + 255) / 256, 256>>>(0, b2);

    // mean over nodes -> d_out[128]
    k_mean1<<<MEAN_B, D>>>();
    k_mean2<<<1, D>>>(out);
}